// round 5
// baseline (speedup 1.0000x reference)
#include <cuda_runtime.h>
#include <cstdint>

// ---------------------------------------------------------------------------
// Problem constants
// ---------------------------------------------------------------------------
#define G_SL   9
#define N_PR   4096
#define D_ORI  2048
#define D_FEAT 512
#define NCLS   21
#define M_TOT  (G_SL * N_PR)          // 36864

#define OFF1 (N_PR * 4)
#define OFF2 (OFF1 + G_SL * N_PR * 4)
#define OFF3 (OFF2 + G_SL * N_PR * NCLS)

// ---------------------------------------------------------------------------
// Device scratch (no cudaMalloc allowed)
// ---------------------------------------------------------------------------
__device__ float g_Bt[(size_t)D_FEAT * D_ORI];   // attention_feat^T, tf32-rounded
__device__ float g_alpha[(size_t)M_TOT * 4];     // alpha logits (atomic accum)
__device__ float g_alphacls[(size_t)M_TOT];      // alpha_cls logits (atomic accum)

// ---------------------------------------------------------------------------
// PTX helpers (baseline ISA only — NO tcgen05 on this toolchain target)
// ---------------------------------------------------------------------------
__device__ __forceinline__ uint32_t smem_u32(const void* p) {
    uint32_t a;
    asm("{ .reg .u64 t; cvta.to.shared.u64 t, %1; cvt.u32.u64 %0, t; }"
        : "=r"(a) : "l"(p));
    return a;
}

#define CP_ASYNC16(dst, src) \
    asm volatile("cp.async.cg.shared.global [%0], [%1], 16;" :: "r"(dst), "l"(src) : "memory")
#define CP_COMMIT() asm volatile("cp.async.commit_group;" ::: "memory")

__device__ __forceinline__ uint32_t f2tf(float x) {
    uint32_t u;
    asm("cvt.rna.tf32.f32 %0, %1;" : "=r"(u) : "f"(x));
    return u;
}

__device__ __forceinline__ void mma_tf32(float* c, const uint32_t* a, const uint32_t* b) {
    asm volatile(
        "mma.sync.aligned.m16n8k8.row.col.f32.tf32.tf32.f32 "
        "{%0,%1,%2,%3}, {%4,%5,%6,%7}, {%8,%9}, {%0,%1,%2,%3};"
        : "+f"(c[0]), "+f"(c[1]), "+f"(c[2]), "+f"(c[3])
        : "r"(a[0]), "r"(a[1]), "r"(a[2]), "r"(a[3]),
          "r"(b[0]), "r"(b[1]));
}

// ---------------------------------------------------------------------------
// Pre-kernel: transpose attention_feat [K=2048, N=512] -> g_Bt [N=512, K=2048]
// tf32-rounded (free rounding for the B operand).
// ---------------------------------------------------------------------------
__global__ void transpose_kernel(const float* __restrict__ B)
{
    __shared__ float tile[32][33];
    const int kx = blockIdx.x * 32;
    const int nx = blockIdx.y * 32;
    const int tx = threadIdx.x, ty = threadIdx.y;   // 32 x 8
#pragma unroll
    for (int j = 0; j < 4; j++)
        tile[ty + j * 8][tx] = B[(size_t)(kx + ty + j * 8) * D_FEAT + nx + tx];
    __syncthreads();
#pragma unroll
    for (int j = 0; j < 4; j++)
        g_Bt[(size_t)(nx + ty + j * 8) * D_ORI + kx + tx] =
            __uint_as_float(f2tf(tile[tx][ty + j * 8]));
}

// ---------------------------------------------------------------------------
// FUSED kernel: per CTA tile (128 rows x 256 feat-cols, grid (2, 288)):
//   - GEMM acc = features @ attention_feat (tf32 mma), K-pipelined cp.async
//   - bx==0 CTAs additionally: branch = features @ [bbox|cls] (128x32 mma)
//   - epilogue: relu in regs; alpha/alpha_cls partials -> atomicAdd;
//               bx==0: dpo = delta_rois+offset -> out1, cls softmax -> out2.
//   features is streamed from DRAM exactly twice total (L2-adjacent).
// ---------------------------------------------------------------------------
#define BM 128
#define BN 256
#define BK 32
#define PAD 36
#define KITERS (D_ORI / BK)                 // 64
#define ASTG (BM * PAD)                     // 4608 floats
#define BSTG (BN * PAD)                     // 9216 floats
#define STG  (ASTG + BSTG)                  // 13824 floats
#define WSTG (32 * PAD)                     // 1152 floats (weight stage)
#define SMEM_FUSED_TOTAL ((3 * STG + 2 * WSTG) * 4)   // 175104 bytes

__global__ __launch_bounds__(256, 1)
void fused_kernel(const float* __restrict__ A,
                  const float* __restrict__ alpha_w,      // [G, 512, 4]
                  const float* __restrict__ alpha_w_cls,  // [G, 512, 1]
                  const float* __restrict__ bbox_w,       // [G, 2048, 4]
                  const float* __restrict__ cls_w,        // [G, 2048, 21]
                  const float* __restrict__ delta_rois,   // [G, N, 5]
                  float* __restrict__ dpo_out,            // out1 [G,N,4]
                  float* __restrict__ cls_out)            // out2 [G,N,21]
{
    extern __shared__ float smf[];
    const uint32_t sb = smem_u32(smf);
    const int tid  = threadIdx.x;
    const int wid  = tid >> 5;
    const int lane = tid & 31;
    const int r  = lane >> 2;
    const int cq = lane & 3;

    const int bx = blockIdx.x;               // 0 or 1 (feat col half)
    const int m0 = blockIdx.y * BM;          // global row in [M_TOT]
    const int n0 = bx * BN;
    const int g  = blockIdx.y >> 5;          // 32 M-tiles per g
    const int mbase = (wid & 1) * 64;
    const int nbase = (wid >> 1) * 64;
    const bool do_br = (bx == 0);

    const float* Abase = A + (size_t)m0 * D_ORI;
    const float* Bbase = g_Bt + (size_t)n0 * D_ORI;
    float* Wst = smf + 3 * STG;               // [2][32][PAD]

    float acc[4][8][4];
#pragma unroll
    for (int mt = 0; mt < 4; mt++)
#pragma unroll
        for (int nt = 0; nt < 8; nt++)
#pragma unroll
            for (int i = 0; i < 4; i++) acc[mt][nt][i] = 0.f;

    float accb[4][4];
#pragma unroll
    for (int nt = 0; nt < 4; nt++)
#pragma unroll
        for (int i = 0; i < 4; i++) accb[nt][i] = 0.f;

    auto load_stage = [&](int kiter, int slot) {
        const int k0 = kiter * BK;
        const uint32_t base = sb + slot * (STG * 4);
#pragma unroll
        for (int i = 0; i < 4; i++) {                 // A: 1024 x 16B
            int c = tid + i * 256;
            int row = c >> 3, kc = c & 7;
            CP_ASYNC16(base + row * (PAD * 4) + kc * 16,
                       Abase + (size_t)row * D_ORI + k0 + kc * 4);
        }
#pragma unroll
        for (int i = 0; i < 8; i++) {                 // B: 2048 x 16B
            int c = tid + i * 256;
            int row = c >> 3, kc = c & 7;
            CP_ASYNC16(base + ASTG * 4 + row * (PAD * 4) + kc * 16,
                       Bbase + (size_t)row * D_ORI + k0 + kc * 4);
        }
        CP_COMMIT();
    };

    // branch weight prefetch (plain LDG, reg-staged one k-iter ahead)
    auto wload = [&](int k0, float* wr) {
        const int col = lane;
#pragma unroll
        for (int i = 0; i < 4; i++) {
            const int d = k0 + wid + 8 * i;
            float w = 0.f;
            if (col < 4)       w = bbox_w[((size_t)g * D_ORI + d) * 4 + col];
            else if (col < 25) w = cls_w[((size_t)g * D_ORI + d) * 21 + col - 4];
            wr[i] = w;
        }
    };

    float wreg[4] = {0.f, 0.f, 0.f, 0.f};
    if (do_br) wload(0, wreg);
    load_stage(0, 0);
    load_stage(1, 1);

    for (int k = 0; k < KITERS; k++) {
        const int slot = k % 3;
        const int ws   = k & 1;

        if (k < KITERS - 2) asm volatile("cp.async.wait_group 1;" ::: "memory");
        else                asm volatile("cp.async.wait_group 0;" ::: "memory");

        if (do_br) {     // stage prefetched weights into smem buffer ws
            float* W = Wst + ws * WSTG;
#pragma unroll
            for (int i = 0; i < 4; i++)
                W[lane * PAD + wid + 8 * i] = wreg[i];
        }
        __syncthreads();

        if (do_br && k + 1 < KITERS) wload((k + 1) * BK, wreg);
        if (k + 2 < KITERS) load_stage(k + 2, (k + 2) % 3);

        const float* As0 = smf + slot * STG;
        const float* Bs0 = As0 + ASTG;
        const float* Ws0 = Wst + ws * WSTG;

#pragma unroll
        for (int kk = 0; kk < 4; kk++) {
            // A fragments: raw fp32 bits (implicit tf32 truncation in HW)
            uint32_t af[4][4];
#pragma unroll
            for (int mt = 0; mt < 4; mt++) {
                const float* p = As0 + (mbase + mt * 16 + r) * PAD + kk * 8 + cq;
                af[mt][0] = __float_as_uint(p[0]);
                af[mt][1] = __float_as_uint(p[8 * PAD]);
                af[mt][2] = __float_as_uint(p[4]);
                af[mt][3] = __float_as_uint(p[8 * PAD + 4]);
            }
            uint32_t bf[8][2];
#pragma unroll
            for (int nt = 0; nt < 8; nt++) {
                const float* q = Bs0 + (nbase + nt * 8 + r) * PAD + kk * 8 + cq;
                bf[nt][0] = __float_as_uint(q[0]);   // pre-rounded tf32
                bf[nt][1] = __float_as_uint(q[4]);
            }
#pragma unroll
            for (int mt = 0; mt < 4; mt++)
#pragma unroll
                for (int nt = 0; nt < 8; nt++)
                    mma_tf32(acc[mt][nt], af[mt], bf[nt]);

            if (do_br) {  // branch mma: warp wid owns rows wid*16..+15
                uint32_t ab[4];
                const float* p = As0 + (wid * 16 + r) * PAD + kk * 8 + cq;
                ab[0] = __float_as_uint(p[0]);
                ab[1] = __float_as_uint(p[8 * PAD]);
                ab[2] = __float_as_uint(p[4]);
                ab[3] = __float_as_uint(p[8 * PAD + 4]);
#pragma unroll
                for (int nt = 0; nt < 4; nt++) {
                    const float* q = Ws0 + (nt * 8 + r) * PAD + kk * 8 + cq;
                    uint32_t wb[2];
                    wb[0] = __float_as_uint(q[0]);
                    wb[1] = __float_as_uint(q[4]);
                    mma_tf32(accb[nt], ab, wb);
                }
            }
        }
    }

    // ---- relu in registers ----
#pragma unroll
    for (int mt = 0; mt < 4; mt++)
#pragma unroll
        for (int nt = 0; nt < 8; nt++)
#pragma unroll
            for (int i = 0; i < 4; i++) acc[mt][nt][i] = fmaxf(acc[mt][nt][i], 0.f);

    __syncthreads();

    // ---- stage alpha weights [256 cols][6] + branch logits [128][33] ----
    float* wA = smf;                 // 1536 floats
    float* sT = smf + 2048;          // 4224 floats
    {
        const int c = tid;           // 256 threads == 256 cols
#pragma unroll
        for (int f = 0; f < 4; f++)
            wA[c * 6 + f] = alpha_w[((size_t)g * D_FEAT + n0 + c) * 4 + f];
        wA[c * 6 + 4] = alpha_w_cls[(size_t)g * D_FEAT + n0 + c];
    }
    if (do_br) {
#pragma unroll
        for (int nt = 0; nt < 4; nt++) {
            const int c0 = nt * 8 + cq * 2;
            const int r0 = wid * 16 + r;
            sT[r0 * 33 + c0]           = accb[nt][0];
            sT[r0 * 33 + c0 + 1]       = accb[nt][1];
            sT[(r0 + 8) * 33 + c0]     = accb[nt][2];
            sT[(r0 + 8) * 33 + c0 + 1] = accb[nt][3];
        }
    }
    __syncthreads();

    // ---- alpha partials: shuffle-reduce over quad, atomicAdd ----
#pragma unroll
    for (int mt = 0; mt < 4; mt++) {
#pragma unroll
        for (int h = 0; h < 2; h++) {
            float s[5] = {0.f, 0.f, 0.f, 0.f, 0.f};
#pragma unroll
            for (int nt = 0; nt < 8; nt++) {
                const int col = nbase + nt * 8 + cq * 2;
                const float v0 = acc[mt][nt][2 * h + 0];
                const float v1 = acc[mt][nt][2 * h + 1];
#pragma unroll
                for (int f = 0; f < 5; f++)
                    s[f] += v0 * wA[col * 6 + f] + v1 * wA[(col + 1) * 6 + f];
            }
#pragma unroll
            for (int f = 0; f < 5; f++) {
                s[f] += __shfl_xor_sync(0xFFFFFFFF, s[f], 1);
                s[f] += __shfl_xor_sync(0xFFFFFFFF, s[f], 2);
            }
            if (cq == 0) {
                const int grow = m0 + mbase + mt * 16 + h * 8 + r;
#pragma unroll
                for (int f = 0; f < 4; f++)
                    atomicAdd(&g_alpha[(size_t)grow * 4 + f], s[f]);
                atomicAdd(&g_alphacls[grow], s[4]);
            }
        }
    }

    // ---- branch epilogue: dpo + cls softmax (bx==0, 128 threads) ----
    if (do_br && tid < 128) {
        const int row = tid;
        const size_t gn = (size_t)(m0 + row);
        const float* L = sT + row * 33;

#pragma unroll
        for (int f = 0; f < 4; f++)
            dpo_out[gn * 4 + f] = delta_rois[gn * 5 + 1 + f] + L[f];

        float m = L[4];
#pragma unroll
        for (int c = 1; c < NCLS; c++) m = fmaxf(m, L[4 + c]);
        float e[NCLS], sm = 0.f;
#pragma unroll
        for (int c = 0; c < NCLS; c++) {
            e[c] = expf(L[4 + c] - m);
            sm += e[c];
        }
        const float inv = 1.f / sm;
#pragma unroll
        for (int c = 0; c < NCLS; c++)
            cls_out[gn * NCLS + c] = e[c] * inv;
    }
}

// ---------------------------------------------------------------------------
// Kernel C: softmax over G + final weighted sum
// ---------------------------------------------------------------------------
__global__ void finalize_kernel(const float* __restrict__ dpo,
                                float* __restrict__ out0,
                                float* __restrict__ out3)
{
    int n = blockIdx.x * blockDim.x + threadIdx.x;
    if (n >= N_PR) return;

#pragma unroll
    for (int f = 0; f < 4; f++) {
        float a[G_SL];
        float m = -1e30f;
#pragma unroll
        for (int g = 0; g < G_SL; g++) {
            a[g] = g_alpha[((size_t)g * N_PR + n) * 4 + f];
            m = fmaxf(m, a[g]);
        }
        float s = 0.f;
#pragma unroll
        for (int g = 0; g < G_SL; g++) {
            a[g] = expf(a[g] - m);
            s += a[g];
        }
        float inv = 1.f / s;
        float o = 0.f;
#pragma unroll
        for (int g = 0; g < G_SL; g++)
            o += dpo[((size_t)g * N_PR + n) * 4 + f] * a[g] * inv;
        out0[(size_t)n * 4 + f] = o;
    }

    {
        float a[G_SL];
        float m = -1e30f;
#pragma unroll
        for (int g = 0; g < G_SL; g++) {
            a[g] = g_alphacls[(size_t)g * N_PR + n];
            m = fmaxf(m, a[g]);
        }
        float s = 0.f;
#pragma unroll
        for (int g = 0; g < G_SL; g++) {
            a[g] = expf(a[g] - m);
            s += a[g];
        }
        float inv = 1.f / s;
#pragma unroll
        for (int g = 0; g < G_SL; g++)
            out3[(size_t)g * N_PR + n] = a[g] * inv;
    }
}

// ---------------------------------------------------------------------------
// Launch
// ---------------------------------------------------------------------------
extern "C" void kernel_launch(void* const* d_in, const int* in_sizes, int n_in,
                              void* d_out, int out_size)
{
    const float* features     = (const float*)d_in[0];
    const float* delta_rois   = (const float*)d_in[3];
    const float* attention    = (const float*)d_in[5];
    const float* alpha_w      = (const float*)d_in[6];
    const float* bbox_regress = (const float*)d_in[7];
    const float* alpha_w_cls  = (const float*)d_in[8];
    const float* cls_w        = (const float*)d_in[9];

    float* out  = (float*)d_out;
    float* out0 = out;
    float* out1 = out + OFF1;
    float* out2 = out + OFF2;
    float* out3 = out + OFF3;

    static bool attr_set = false;
    if (!attr_set) {
        cudaFuncSetAttribute(fused_kernel,
                             cudaFuncAttributeMaxDynamicSharedMemorySize,
                             SMEM_FUSED_TOTAL);
        attr_set = true;
    }

    // zero the atomic accumulators (graph-capturable)
    void* pA; cudaGetSymbolAddress(&pA, g_alpha);
    void* pC; cudaGetSymbolAddress(&pC, g_alphacls);
    cudaMemsetAsync(pA, 0, sizeof(float) * (size_t)M_TOT * 4, 0);
    cudaMemsetAsync(pC, 0, sizeof(float) * (size_t)M_TOT, 0);

    // transpose attention_feat to [N, K] (K-major, tf32-rounded)
    transpose_kernel<<<dim3(D_ORI / 32, D_FEAT / 32), dim3(32, 8)>>>(attention);

    // fused GEMM + relu + alpha projection + branch GEMM + softmax/dpo
    fused_kernel<<<dim3(2, M_TOT / BM), 256, SMEM_FUSED_TOTAL>>>(
        features, alpha_w, alpha_w_cls, bbox_regress, cls_w, delta_rois,
        out1, out2);

    // softmax over G + final output
    finalize_kernel<<<(N_PR + 255) / 256, 256>>>(out1, out0, out3);
}

// round 6
// speedup vs baseline: 1.4839x; 1.4839x over previous
#include <cuda_runtime.h>
#include <cuda_fp16.h>
#include <cstdint>

// ---------------------------------------------------------------------------
// Problem constants
// ---------------------------------------------------------------------------
#define G_SL   9
#define N_PR   4096
#define D_ORI  2048
#define D_FEAT 512
#define NCLS   21
#define M_TOT  (G_SL * N_PR)          // 36864

#define OFF1 (N_PR * 4)
#define OFF2 (OFF1 + G_SL * N_PR * 4)
#define OFF3 (OFF2 + G_SL * N_PR * NCLS)

// ---------------------------------------------------------------------------
// Device scratch (no cudaMalloc allowed)
// ---------------------------------------------------------------------------
__device__ __half g_Ah[(size_t)M_TOT * D_ORI];   // features, fp16 (151 MB)
__device__ __half g_Bh[(size_t)D_ORI * D_FEAT];  // attention_feat, fp16 [K][N]
__device__ float  g_alpha[(size_t)M_TOT * 4];    // alpha logits (atomic accum)
__device__ float  g_alphacls[(size_t)M_TOT];     // alpha_cls logits (atomic accum)

// ---------------------------------------------------------------------------
// PTX helpers (baseline ISA only — NO tcgen05 on this toolchain target)
// ---------------------------------------------------------------------------
__device__ __forceinline__ uint32_t smem_u32(const void* p) {
    uint32_t a;
    asm("{ .reg .u64 t; cvta.to.shared.u64 t, %1; cvt.u32.u64 %0, t; }"
        : "=r"(a) : "l"(p));
    return a;
}

#define CP_ASYNC16(dst, src) \
    asm volatile("cp.async.cg.shared.global [%0], [%1], 16;" :: "r"(dst), "l"(src) : "memory")
#define CP_COMMIT() asm volatile("cp.async.commit_group;" ::: "memory")

__device__ __forceinline__ void ldsm_x4(uint32_t* r, uint32_t addr) {
    asm volatile("ldmatrix.sync.aligned.m8n8.x4.shared.b16 {%0,%1,%2,%3}, [%4];"
        : "=r"(r[0]), "=r"(r[1]), "=r"(r[2]), "=r"(r[3]) : "r"(addr));
}
__device__ __forceinline__ void ldsm_x4t(uint32_t* r, uint32_t addr) {
    asm volatile("ldmatrix.sync.aligned.m8n8.x4.trans.shared.b16 {%0,%1,%2,%3}, [%4];"
        : "=r"(r[0]), "=r"(r[1]), "=r"(r[2]), "=r"(r[3]) : "r"(addr));
}

__device__ __forceinline__ void mma_f16(float* c, const uint32_t* a, const uint32_t* b) {
    asm volatile(
        "mma.sync.aligned.m16n8k16.row.col.f32.f16.f16.f32 "
        "{%0,%1,%2,%3}, {%4,%5,%6,%7}, {%8,%9}, {%0,%1,%2,%3};"
        : "+f"(c[0]), "+f"(c[1]), "+f"(c[2]), "+f"(c[3])
        : "r"(a[0]), "r"(a[1]), "r"(a[2]), "r"(a[3]),
          "r"(b[0]), "r"(b[1]));
}

// ---------------------------------------------------------------------------
// Conversion kernel: f32 -> f16, 8 elements per thread
// ---------------------------------------------------------------------------
__global__ void convert_kernel(const float* __restrict__ src,
                               __half* __restrict__ dst, int n8)
{
    int i = blockIdx.x * blockDim.x + threadIdx.x;
    if (i >= n8) return;
    float4 v0 = reinterpret_cast<const float4*>(src)[2 * i];
    float4 v1 = reinterpret_cast<const float4*>(src)[2 * i + 1];
    __half2 h0 = __floats2half2_rn(v0.x, v0.y);
    __half2 h1 = __floats2half2_rn(v0.z, v0.w);
    __half2 h2 = __floats2half2_rn(v1.x, v1.y);
    __half2 h3 = __floats2half2_rn(v1.z, v1.w);
    uint4 o;
    o.x = *reinterpret_cast<uint32_t*>(&h0);
    o.y = *reinterpret_cast<uint32_t*>(&h1);
    o.z = *reinterpret_cast<uint32_t*>(&h2);
    o.w = *reinterpret_cast<uint32_t*>(&h3);
    reinterpret_cast<uint4*>(dst)[i] = o;
}

// ---------------------------------------------------------------------------
// Kernel A: fused GEMM + relu + alpha projection (fp16 mma, ldmatrix).
//   CTA tile 128x256, BK=32, 3-stage cp.async, warp tile 64x64.
//   A smem: [128][40] f16 (pad 40), B smem: [32][264] f16 (pad 264, [k][n]).
// ---------------------------------------------------------------------------
#define BM 128
#define BN 256
#define BK 32
#define APAD 40
#define BPAD 264
#define KITERS (D_ORI / BK)                  // 64
#define ASTGB (BM * APAD * 2)                // 10240 bytes
#define BSTGB (BK * BPAD * 2)                // 16896 bytes
#define STGB  (ASTGB + BSTGB)                // 27136 bytes
#define SMEM_GEMM_TOTAL (3 * STGB)           // 81408 bytes

__global__ __launch_bounds__(256, 1)
void gemm_alpha_kernel(const float* __restrict__ alpha_w,      // [G, 512, 4]
                       const float* __restrict__ alpha_w_cls)  // [G, 512, 1]
{
    extern __shared__ char smem[];
    const uint32_t sb = smem_u32(smem);
    const int tid  = threadIdx.x;
    const int wid  = tid >> 5;
    const int lane = tid & 31;
    const int r  = lane >> 2;
    const int cq = lane & 3;
    const int q  = lane >> 3;      // ldmatrix lane group 0..3
    const int t  = lane & 7;

    const int m0 = blockIdx.y * BM;
    const int n0 = blockIdx.x * BN;
    const int g  = blockIdx.y >> 5;
    const int mbase = (wid & 1) * 64;
    const int nbase = (wid >> 1) * 64;

    const __half* Abase = g_Ah + (size_t)m0 * D_ORI;
    const __half* Bbase = g_Bh + n0;

    float acc[4][8][4];
#pragma unroll
    for (int mt = 0; mt < 4; mt++)
#pragma unroll
        for (int nt = 0; nt < 8; nt++)
#pragma unroll
            for (int i = 0; i < 4; i++) acc[mt][nt][i] = 0.f;

    auto load_stage = [&](int kiter, int slot) {
        const int k0 = kiter * BK;
        const uint32_t sA = sb + slot * STGB;
        const uint32_t sB = sA + ASTGB;
        // A: 128 rows x 64B = 512 chunks
#pragma unroll
        for (int i = 0; i < 2; i++) {
            int c = tid + i * 256;
            int row = c >> 2, c16 = c & 3;
            CP_ASYNC16(sA + row * (APAD * 2) + c16 * 16,
                       Abase + (size_t)row * D_ORI + k0 + c16 * 8);
        }
        // B: 32 k-rows x 512B = 1024 chunks
#pragma unroll
        for (int i = 0; i < 4; i++) {
            int c = tid + i * 256;
            int krow = c >> 5, c16 = c & 31;
            CP_ASYNC16(sB + krow * (BPAD * 2) + c16 * 16,
                       Bbase + (size_t)(k0 + krow) * D_FEAT + c16 * 8);
        }
        CP_COMMIT();
    };

    load_stage(0, 0);
    load_stage(1, 1);

    for (int k = 0; k < KITERS; k++) {
        const int slot = k % 3;

        if (k < KITERS - 2) asm volatile("cp.async.wait_group 1;" ::: "memory");
        else                asm volatile("cp.async.wait_group 0;" ::: "memory");
        __syncthreads();

        if (k + 2 < KITERS) load_stage(k + 2, (k + 2) % 3);

        const uint32_t sA = sb + slot * STGB;
        const uint32_t sB = sA + ASTGB;

#pragma unroll
        for (int kk = 0; kk < 2; kk++) {
            // A frags: 4 x ldmatrix.x4 (m16k16 each)
            uint32_t af[4][4];
#pragma unroll
            for (int mt = 0; mt < 4; mt++) {
                const int arow = mbase + mt * 16 + (q & 1) * 8 + t;
                const int acol = kk * 16 + (q >> 1) * 8;
                ldsm_x4(af[mt], sA + (arow * APAD + acol) * 2);
            }
            // B frags: 4 x ldmatrix.x4.trans (k16n16 each -> 2 n8 frags)
            uint32_t bf[4][4];
#pragma unroll
            for (int p = 0; p < 4; p++) {
                const int krow = kk * 16 + (q & 1) * 8 + t;
                const int ncol = nbase + p * 16 + (q >> 1) * 8;
                ldsm_x4t(bf[p], sB + (krow * BPAD + ncol) * 2);
            }
#pragma unroll
            for (int mt = 0; mt < 4; mt++)
#pragma unroll
                for (int nt = 0; nt < 8; nt++)
                    mma_f16(acc[mt][nt], af[mt], &bf[nt >> 1][(nt & 1) * 2]);
        }
    }

    // ---- relu in registers ----
#pragma unroll
    for (int mt = 0; mt < 4; mt++)
#pragma unroll
        for (int nt = 0; nt < 8; nt++)
#pragma unroll
            for (int i = 0; i < 4; i++) acc[mt][nt][i] = fmaxf(acc[mt][nt][i], 0.f);

    // ---- stage alpha weights for this CTA's 256 columns ----
    __syncthreads();
    float* wA = reinterpret_cast<float*>(smem);     // [256][6]
    {
        const int c = tid;
#pragma unroll
        for (int f = 0; f < 4; f++)
            wA[c * 6 + f] = alpha_w[((size_t)g * D_FEAT + n0 + c) * 4 + f];
        wA[c * 6 + 4] = alpha_w_cls[(size_t)g * D_FEAT + n0 + c];
    }
    __syncthreads();

    // ---- alpha partials: per row dot over 16 owned cols, quad-reduce ----
#pragma unroll
    for (int mt = 0; mt < 4; mt++) {
#pragma unroll
        for (int h = 0; h < 2; h++) {
            float s[5] = {0.f, 0.f, 0.f, 0.f, 0.f};
#pragma unroll
            for (int nt = 0; nt < 8; nt++) {
                const int col = nbase + nt * 8 + cq * 2;
                const float v0 = acc[mt][nt][2 * h + 0];
                const float v1 = acc[mt][nt][2 * h + 1];
#pragma unroll
                for (int f = 0; f < 5; f++)
                    s[f] += v0 * wA[col * 6 + f] + v1 * wA[(col + 1) * 6 + f];
            }
#pragma unroll
            for (int f = 0; f < 5; f++) {
                s[f] += __shfl_xor_sync(0xFFFFFFFF, s[f], 1);
                s[f] += __shfl_xor_sync(0xFFFFFFFF, s[f], 2);
            }
            if (cq == 0) {
                const int grow = m0 + mbase + mt * 16 + h * 8 + r;
#pragma unroll
                for (int f = 0; f < 4; f++)
                    atomicAdd(&g_alpha[(size_t)grow * 4 + f], s[f]);
                atomicAdd(&g_alphacls[grow], s[4]);
            }
        }
    }
}

// ---------------------------------------------------------------------------
// Kernel B: branch GEMM (fp16 mma): per (g, 128-row tile):
//   [128 x 2048] @ [2048 x 32] -> offset(4)+cls(21). Epilogue: dpo + softmax.
//   A: 3-stage cp.async (fp16). W: reg-prefetch -> smem double buffer [k][40n].
// ---------------------------------------------------------------------------
#define WSTGH (BK * APAD)                         // 1280 halves per W stage
#define SMEM_BR_TOTAL (3 * ASTGB + 2 * WSTGH * 2) // 35840 bytes

__global__ __launch_bounds__(256, 1)
void branch_kernel(const float* __restrict__ bbox_w,      // [G, D_ORI, 4]
                   const float* __restrict__ cls_w,       // [G, D_ORI, 21]
                   const float* __restrict__ delta_rois,  // [G, N, 5]
                   float* __restrict__ dpo_out,           // out1 [G,N,4]
                   float* __restrict__ cls_out)           // out2 [G,N,21]
{
    extern __shared__ char smem[];
    const uint32_t sb = smem_u32(smem);
    const int tid  = threadIdx.x;
    const int wid  = tid >> 5;
    const int lane = tid & 31;
    const int cq = lane & 3;
    const int q  = lane >> 3;
    const int t  = lane & 7;

    const int g  = blockIdx.y;
    const int n0 = blockIdx.x * 128;

    const __half* Abase = g_Ah + ((size_t)g * N_PR + n0) * D_ORI;
    __half* Wst = reinterpret_cast<__half*>(smem + 3 * ASTGB);   // [2][32][40]

    float acc[4][4];
#pragma unroll
    for (int nt = 0; nt < 4; nt++)
#pragma unroll
        for (int i = 0; i < 4; i++) acc[nt][i] = 0.f;

    auto wload = [&](int k0, float* wr) {
        const int col = lane;
#pragma unroll
        for (int i = 0; i < 4; i++) {
            const int d = k0 + wid + 8 * i;
            float w = 0.f;
            if (col < 4)       w = bbox_w[((size_t)g * D_ORI + d) * 4 + col];
            else if (col < 25) w = cls_w[((size_t)g * D_ORI + d) * 21 + col - 4];
            wr[i] = w;
        }
    };
    auto aload = [&](int kiter, int slot) {
        const uint32_t sA = sb + slot * ASTGB;
        const int k0 = kiter * BK;
#pragma unroll
        for (int i = 0; i < 2; i++) {
            int c = tid + i * 256;
            int row = c >> 2, c16 = c & 3;
            CP_ASYNC16(sA + row * (APAD * 2) + c16 * 16,
                       Abase + (size_t)row * D_ORI + k0 + c16 * 8);
        }
        CP_COMMIT();
    };

    float wreg[4];
    wload(0, wreg);
    aload(0, 0);
    aload(1, 1);

    for (int k = 0; k < KITERS; k++) {
        const int slot = k % 3;
        const int ws   = k & 1;

        if (k < KITERS - 2) asm volatile("cp.async.wait_group 1;" ::: "memory");
        else                asm volatile("cp.async.wait_group 0;" ::: "memory");

        {   // stage prefetched weights as fp16 into buffer ws: [k][n] pad 40
            __half* W = Wst + ws * WSTGH;
#pragma unroll
            for (int i = 0; i < 4; i++)
                W[(wid + 8 * i) * APAD + lane] = __float2half_rn(wreg[i]);
        }
        __syncthreads();

        if (k + 1 < KITERS) wload((k + 1) * BK, wreg);
        if (k + 2 < KITERS) aload(k + 2, (k + 2) % 3);

        const uint32_t sA = sb + slot * ASTGB;
        const uint32_t sW = sb + 3 * ASTGB + ws * (WSTGH * 2);

#pragma unroll
        for (int kk = 0; kk < 2; kk++) {
            uint32_t af[4];
            {
                const int arow = wid * 16 + (q & 1) * 8 + t;
                const int acol = kk * 16 + (q >> 1) * 8;
                ldsm_x4(af, sA + (arow * APAD + acol) * 2);
            }
            uint32_t bf[2][4];
#pragma unroll
            for (int p = 0; p < 2; p++) {
                const int krow = kk * 16 + (q & 1) * 8 + t;
                const int ncol = p * 16 + (q >> 1) * 8;
                ldsm_x4t(bf[p], sW + (krow * APAD + ncol) * 2);
            }
#pragma unroll
            for (int nt = 0; nt < 4; nt++)
                mma_f16(acc[nt], af, &bf[nt >> 1][(nt & 1) * 2]);
        }
        __syncthreads();
    }

    // ---- epilogue: stage logits to smem, then per-row softmax/dpo ----
    float* sT = reinterpret_cast<float*>(smem);     // [128][33]
    {
        const int r0 = wid * 16 + (lane >> 2);
#pragma unroll
        for (int nt = 0; nt < 4; nt++) {
            const int c0 = nt * 8 + cq * 2;
            sT[r0 * 33 + c0]           = acc[nt][0];
            sT[r0 * 33 + c0 + 1]       = acc[nt][1];
            sT[(r0 + 8) * 33 + c0]     = acc[nt][2];
            sT[(r0 + 8) * 33 + c0 + 1] = acc[nt][3];
        }
    }
    __syncthreads();

    if (tid < 128) {
        const int row = tid;
        const size_t gn = (size_t)g * N_PR + n0 + row;
        const float* L = sT + row * 33;

#pragma unroll
        for (int f = 0; f < 4; f++)
            dpo_out[gn * 4 + f] = delta_rois[gn * 5 + 1 + f] + L[f];

        float m = L[4];
#pragma unroll
        for (int c = 1; c < NCLS; c++) m = fmaxf(m, L[4 + c]);
        float e[NCLS], s = 0.f;
#pragma unroll
        for (int c = 0; c < NCLS; c++) {
            e[c] = expf(L[4 + c] - m);
            s += e[c];
        }
        const float inv = 1.f / s;
#pragma unroll
        for (int c = 0; c < NCLS; c++)
            cls_out[gn * NCLS + c] = e[c] * inv;
    }
}

// ---------------------------------------------------------------------------
// Kernel C: softmax over G + final weighted sum
// ---------------------------------------------------------------------------
__global__ void finalize_kernel(const float* __restrict__ dpo,
                                float* __restrict__ out0,
                                float* __restrict__ out3)
{
    int n = blockIdx.x * blockDim.x + threadIdx.x;
    if (n >= N_PR) return;

#pragma unroll
    for (int f = 0; f < 4; f++) {
        float a[G_SL];
        float m = -1e30f;
#pragma unroll
        for (int g = 0; g < G_SL; g++) {
            a[g] = g_alpha[((size_t)g * N_PR + n) * 4 + f];
            m = fmaxf(m, a[g]);
        }
        float s = 0.f;
#pragma unroll
        for (int g = 0; g < G_SL; g++) {
            a[g] = expf(a[g] - m);
            s += a[g];
        }
        float inv = 1.f / s;
        float o = 0.f;
#pragma unroll
        for (int g = 0; g < G_SL; g++)
            o += dpo[((size_t)g * N_PR + n) * 4 + f] * a[g] * inv;
        out0[(size_t)n * 4 + f] = o;
    }

    {
        float a[G_SL];
        float m = -1e30f;
#pragma unroll
        for (int g = 0; g < G_SL; g++) {
            a[g] = g_alphacls[(size_t)g * N_PR + n];
            m = fmaxf(m, a[g]);
        }
        float s = 0.f;
#pragma unroll
        for (int g = 0; g < G_SL; g++) {
            a[g] = expf(a[g] - m);
            s += a[g];
        }
        float inv = 1.f / s;
#pragma unroll
        for (int g = 0; g < G_SL; g++)
            out3[(size_t)g * N_PR + n] = a[g] * inv;
    }
}

// ---------------------------------------------------------------------------
// Launch
// ---------------------------------------------------------------------------
extern "C" void kernel_launch(void* const* d_in, const int* in_sizes, int n_in,
                              void* d_out, int out_size)
{
    const float* features     = (const float*)d_in[0];
    const float* delta_rois   = (const float*)d_in[3];
    const float* attention    = (const float*)d_in[5];
    const float* alpha_w      = (const float*)d_in[6];
    const float* bbox_regress = (const float*)d_in[7];
    const float* alpha_w_cls  = (const float*)d_in[8];
    const float* cls_w        = (const float*)d_in[9];

    float* out  = (float*)d_out;
    float* out0 = out;
    float* out1 = out + OFF1;
    float* out2 = out + OFF2;
    float* out3 = out + OFF3;

    static bool attr_set = false;
    if (!attr_set) {
        cudaFuncSetAttribute(gemm_alpha_kernel,
                             cudaFuncAttributeMaxDynamicSharedMemorySize,
                             SMEM_GEMM_TOTAL);
        cudaFuncSetAttribute(branch_kernel,
                             cudaFuncAttributeMaxDynamicSharedMemorySize,
                             SMEM_BR_TOTAL);
        attr_set = true;
    }

    // zero the atomic accumulators (graph-capturable)
    void* pA; cudaGetSymbolAddress(&pA, g_alpha);
    void* pC; cudaGetSymbolAddress(&pC, g_alphacls);
    cudaMemsetAsync(pA, 0, sizeof(float) * (size_t)M_TOT * 4, 0);
    cudaMemsetAsync(pC, 0, sizeof(float) * (size_t)M_TOT, 0);

    // convert features and attention_feat to fp16
    void* pAh; cudaGetSymbolAddress(&pAh, g_Ah);
    void* pBh; cudaGetSymbolAddress(&pBh, g_Bh);
    {
        int n8 = (M_TOT * D_ORI) / 8;
        convert_kernel<<<(n8 + 255) / 256, 256>>>(features, (__half*)pAh, n8);
        int b8 = (D_ORI * D_FEAT) / 8;
        convert_kernel<<<(b8 + 255) / 256, 256>>>(attention, (__half*)pBh, b8);
    }

    // fused GEMM + relu + alpha projection
    gemm_alpha_kernel<<<dim3(D_FEAT / BN, M_TOT / BM), 256, SMEM_GEMM_TOTAL>>>(
        alpha_w, alpha_w_cls);

    // branch GEMM (offset + cls) + softmax + dpo
    branch_kernel<<<dim3(N_PR / 128, G_SL), 256, SMEM_BR_TOTAL>>>(
        bbox_regress, cls_w, delta_rois, out1, out2);

    // softmax over G + final output
    finalize_kernel<<<(N_PR + 255) / 256, 256>>>(out1, out0, out3);
}

// round 7
// speedup vs baseline: 1.5799x; 1.0647x over previous
#include <cuda_runtime.h>
#include <cuda_fp16.h>
#include <cstdint>

// ---------------------------------------------------------------------------
// Problem constants
// ---------------------------------------------------------------------------
#define G_SL   9
#define N_PR   4096
#define D_ORI  2048
#define D_FEAT 512
#define NCLS   21
#define M_TOT  (G_SL * N_PR)          // 36864

#define OFF1 (N_PR * 4)
#define OFF2 (OFF1 + G_SL * N_PR * 4)
#define OFF3 (OFF2 + G_SL * N_PR * NCLS)

// ---------------------------------------------------------------------------
// Device scratch (no cudaMalloc allowed)
// ---------------------------------------------------------------------------
__device__ __half g_Ah[(size_t)M_TOT * D_ORI];    // features fp16 (151 MB)
__device__ __half g_Bh[(size_t)D_ORI * D_FEAT];   // attention_feat fp16 [K][N]
__device__ __half g_Wh[(size_t)G_SL * D_ORI * 32];// packed branch weights fp16
__device__ float  g_alpha[(size_t)M_TOT * 4];     // alpha logits (atomic accum)
__device__ float  g_alphacls[(size_t)M_TOT];      // alpha_cls logits

// ---------------------------------------------------------------------------
// PTX helpers
// ---------------------------------------------------------------------------
__device__ __forceinline__ uint32_t smem_u32(const void* p) {
    uint32_t a;
    asm("{ .reg .u64 t; cvta.to.shared.u64 t, %1; cvt.u32.u64 %0, t; }"
        : "=r"(a) : "l"(p));
    return a;
}

#define CP_ASYNC16(dst, src) \
    asm volatile("cp.async.cg.shared.global [%0], [%1], 16;" :: "r"(dst), "l"(src) : "memory")
#define CP_COMMIT() asm volatile("cp.async.commit_group;" ::: "memory")

__device__ __forceinline__ void ldsm_x4(uint32_t* r, uint32_t addr) {
    asm volatile("ldmatrix.sync.aligned.m8n8.x4.shared.b16 {%0,%1,%2,%3}, [%4];"
        : "=r"(r[0]), "=r"(r[1]), "=r"(r[2]), "=r"(r[3]) : "r"(addr));
}
__device__ __forceinline__ void ldsm_x4t(uint32_t* r, uint32_t addr) {
    asm volatile("ldmatrix.sync.aligned.m8n8.x4.trans.shared.b16 {%0,%1,%2,%3}, [%4];"
        : "=r"(r[0]), "=r"(r[1]), "=r"(r[2]), "=r"(r[3]) : "r"(addr));
}

__device__ __forceinline__ void mma_f16(float* c, const uint32_t* a, const uint32_t* b) {
    asm volatile(
        "mma.sync.aligned.m16n8k16.row.col.f32.f16.f16.f32 "
        "{%0,%1,%2,%3}, {%4,%5,%6,%7}, {%8,%9}, {%0,%1,%2,%3};"
        : "+f"(c[0]), "+f"(c[1]), "+f"(c[2]), "+f"(c[3])
        : "r"(a[0]), "r"(a[1]), "r"(a[2]), "r"(a[3]),
          "r"(b[0]), "r"(b[1]));
}

// ---------------------------------------------------------------------------
// Conversion kernel: f32 -> f16, 8 elements per thread
// ---------------------------------------------------------------------------
__global__ void convert_kernel(const float* __restrict__ src,
                               __half* __restrict__ dst, int n8)
{
    int i = blockIdx.x * blockDim.x + threadIdx.x;
    if (i >= n8) return;
    float4 v0 = reinterpret_cast<const float4*>(src)[2 * i];
    float4 v1 = reinterpret_cast<const float4*>(src)[2 * i + 1];
    __half2 h0 = __floats2half2_rn(v0.x, v0.y);
    __half2 h1 = __floats2half2_rn(v0.z, v0.w);
    __half2 h2 = __floats2half2_rn(v1.x, v1.y);
    __half2 h3 = __floats2half2_rn(v1.z, v1.w);
    uint4 o;
    o.x = *reinterpret_cast<uint32_t*>(&h0);
    o.y = *reinterpret_cast<uint32_t*>(&h1);
    o.z = *reinterpret_cast<uint32_t*>(&h2);
    o.w = *reinterpret_cast<uint32_t*>(&h3);
    reinterpret_cast<uint4*>(dst)[i] = o;
}

// ---------------------------------------------------------------------------
// Prep: pack branch weights [G][2048 k][32 n] fp16 (cols 0-3 bbox, 4-24 cls)
// ---------------------------------------------------------------------------
__global__ void pack_weights_kernel(const float* __restrict__ bbox_w,
                                    const float* __restrict__ cls_w)
{
    int idx = blockIdx.x * blockDim.x + threadIdx.x;   // over G*2048
    if (idx >= G_SL * D_ORI) return;
    const int g = idx / D_ORI;
    const int d = idx % D_ORI;
    __half w[32];
#pragma unroll
    for (int c = 0; c < 4; c++)
        w[c] = __float2half_rn(bbox_w[((size_t)g * D_ORI + d) * 4 + c]);
#pragma unroll
    for (int c = 0; c < 21; c++)
        w[4 + c] = __float2half_rn(cls_w[((size_t)g * D_ORI + d) * 21 + c]);
#pragma unroll
    for (int c = 25; c < 32; c++) w[c] = __half(0.f);
    uint4* dst = reinterpret_cast<uint4*>(g_Wh + (size_t)idx * 32);
    const uint4* srcv = reinterpret_cast<const uint4*>(w);
#pragma unroll
    for (int i = 0; i < 4; i++) dst[i] = srcv[i];
}

// ---------------------------------------------------------------------------
// Kernel A: fused GEMM + relu + alpha projection (fp16 mma, ldmatrix).
//   CTA tile 128x256, BK=32, 3-stage cp.async, 512 threads, warp tile 32x64.
// ---------------------------------------------------------------------------
#define BM 128
#define BN 256
#define BK 32
#define APAD 40
#define BPAD 264
#define KITERS (D_ORI / BK)                  // 64
#define ASTGB (BM * APAD * 2)                // 10240 bytes
#define BSTGB (BK * BPAD * 2)                // 16896 bytes
#define STGB  (ASTGB + BSTGB)                // 27136 bytes
#define SMEM_GEMM_TOTAL (3 * STGB)           // 81408 bytes

__global__ __launch_bounds__(512, 1)
void gemm_alpha_kernel(const float* __restrict__ alpha_w,      // [G, 512, 4]
                       const float* __restrict__ alpha_w_cls)  // [G, 512, 1]
{
    extern __shared__ char smem[];
    const uint32_t sb = smem_u32(smem);
    const int tid  = threadIdx.x;
    const int wid  = tid >> 5;     // 0..15
    const int lane = tid & 31;
    const int r  = lane >> 2;
    const int cq = lane & 3;
    const int q  = lane >> 3;
    const int t  = lane & 7;

    const int m0 = blockIdx.y * BM;
    const int n0 = blockIdx.x * BN;
    const int g  = blockIdx.y >> 5;
    const int mbase = (wid & 3) * 32;     // 4 warp rows of 32
    const int nbase = (wid >> 2) * 64;    // 4 warp cols of 64

    const __half* Abase = g_Ah + (size_t)m0 * D_ORI;
    const __half* Bbase = g_Bh + n0;

    float acc[2][8][4];
#pragma unroll
    for (int mt = 0; mt < 2; mt++)
#pragma unroll
        for (int nt = 0; nt < 8; nt++)
#pragma unroll
            for (int i = 0; i < 4; i++) acc[mt][nt][i] = 0.f;

    auto load_stage = [&](int kiter, int slot) {
        const int k0 = kiter * BK;
        const uint32_t sA = sb + slot * STGB;
        const uint32_t sB = sA + ASTGB;
        // A: 128 rows x 4 chunks = 512 -> 1 per thread
        {
            int row = tid >> 2, c16 = tid & 3;
            CP_ASYNC16(sA + row * (APAD * 2) + c16 * 16,
                       Abase + (size_t)row * D_ORI + k0 + c16 * 8);
        }
        // B: 32 k-rows x 32 chunks = 1024 -> 2 per thread
#pragma unroll
        for (int i = 0; i < 2; i++) {
            int c = tid + i * 512;
            int krow = c >> 5, c16 = c & 31;
            CP_ASYNC16(sB + krow * (BPAD * 2) + c16 * 16,
                       Bbase + (size_t)(k0 + krow) * D_FEAT + c16 * 8);
        }
        CP_COMMIT();
    };

    load_stage(0, 0);
    load_stage(1, 1);

    for (int k = 0; k < KITERS; k++) {
        const int slot = k % 3;

        if (k < KITERS - 2) asm volatile("cp.async.wait_group 1;" ::: "memory");
        else                asm volatile("cp.async.wait_group 0;" ::: "memory");
        __syncthreads();

        if (k + 2 < KITERS) load_stage(k + 2, (k + 2) % 3);

        const uint32_t sA = sb + slot * STGB;
        const uint32_t sB = sA + ASTGB;

#pragma unroll
        for (int kk = 0; kk < 2; kk++) {
            uint32_t af[2][4];
#pragma unroll
            for (int mt = 0; mt < 2; mt++) {
                const int arow = mbase + mt * 16 + (q & 1) * 8 + t;
                const int acol = kk * 16 + (q >> 1) * 8;
                ldsm_x4(af[mt], sA + (arow * APAD + acol) * 2);
            }
            uint32_t bf[4][4];
#pragma unroll
            for (int p = 0; p < 4; p++) {
                const int krow = kk * 16 + (q & 1) * 8 + t;
                const int ncol = nbase + p * 16 + (q >> 1) * 8;
                ldsm_x4t(bf[p], sB + (krow * BPAD + ncol) * 2);
            }
#pragma unroll
            for (int mt = 0; mt < 2; mt++)
#pragma unroll
                for (int nt = 0; nt < 8; nt++)
                    mma_f16(acc[mt][nt], af[mt], &bf[nt >> 1][(nt & 1) * 2]);
        }
    }

    // ---- relu in registers ----
#pragma unroll
    for (int mt = 0; mt < 2; mt++)
#pragma unroll
        for (int nt = 0; nt < 8; nt++)
#pragma unroll
            for (int i = 0; i < 4; i++) acc[mt][nt][i] = fmaxf(acc[mt][nt][i], 0.f);

    // ---- stage alpha weights for this CTA's 256 columns ----
    __syncthreads();
    float* wA = reinterpret_cast<float*>(smem);     // [256][6]
    if (tid < 256) {
        const int c = tid;
#pragma unroll
        for (int f = 0; f < 4; f++)
            wA[c * 6 + f] = alpha_w[((size_t)g * D_FEAT + n0 + c) * 4 + f];
        wA[c * 6 + 4] = alpha_w_cls[(size_t)g * D_FEAT + n0 + c];
    }
    __syncthreads();

    // ---- alpha partials: per row dot over 16 owned cols, quad-reduce ----
#pragma unroll
    for (int mt = 0; mt < 2; mt++) {
#pragma unroll
        for (int h = 0; h < 2; h++) {
            float s[5] = {0.f, 0.f, 0.f, 0.f, 0.f};
#pragma unroll
            for (int nt = 0; nt < 8; nt++) {
                const int col = nbase + nt * 8 + cq * 2;
                const float v0 = acc[mt][nt][2 * h + 0];
                const float v1 = acc[mt][nt][2 * h + 1];
#pragma unroll
                for (int f = 0; f < 5; f++)
                    s[f] += v0 * wA[col * 6 + f] + v1 * wA[(col + 1) * 6 + f];
            }
#pragma unroll
            for (int f = 0; f < 5; f++) {
                s[f] += __shfl_xor_sync(0xFFFFFFFF, s[f], 1);
                s[f] += __shfl_xor_sync(0xFFFFFFFF, s[f], 2);
            }
            if (cq == 0) {
                const int grow = m0 + mbase + mt * 16 + h * 8 + r;
#pragma unroll
                for (int f = 0; f < 4; f++)
                    atomicAdd(&g_alpha[(size_t)grow * 4 + f], s[f]);
                atomicAdd(&g_alphacls[grow], s[4]);
            }
        }
    }
}

// ---------------------------------------------------------------------------
// Kernel B: branch GEMM (fp16 mma): [128 x 2048] @ [2048 x 32] per (g, tile).
//   A and W both via 4-stage cp.async (packed fp16 weights). One sync/iter.
// ---------------------------------------------------------------------------
#define WPAD 40
#define WSTGB (BK * WPAD * 2)                     // 2560 bytes
#define BSTG2 (ASTGB + WSTGB)                     // 12800 bytes
#define SMEM_BR_TOTAL (4 * BSTG2)                 // 51200 bytes

__global__ __launch_bounds__(256, 2)
void branch_kernel(const float* __restrict__ delta_rois,  // [G, N, 5]
                   float* __restrict__ dpo_out,            // out1 [G,N,4]
                   float* __restrict__ cls_out)            // out2 [G,N,21]
{
    extern __shared__ char smem[];
    const uint32_t sb = smem_u32(smem);
    const int tid  = threadIdx.x;
    const int wid  = tid >> 5;
    const int lane = tid & 31;
    const int cq = lane & 3;
    const int q  = lane >> 3;
    const int t  = lane & 7;

    const int g  = blockIdx.y;
    const int n0 = blockIdx.x * 128;

    const __half* Abase = g_Ah + ((size_t)g * N_PR + n0) * D_ORI;
    const __half* Wbase = g_Wh + (size_t)g * D_ORI * 32;

    float acc[4][4];
#pragma unroll
    for (int nt = 0; nt < 4; nt++)
#pragma unroll
        for (int i = 0; i < 4; i++) acc[nt][i] = 0.f;

    auto load_stage = [&](int kiter, int slot) {
        const int k0 = kiter * BK;
        const uint32_t sA = sb + slot * BSTG2;
        const uint32_t sW = sA + ASTGB;
        // A: 128 rows x 4 chunks = 512 -> 2 per thread
#pragma unroll
        for (int i = 0; i < 2; i++) {
            int c = tid + i * 256;
            int row = c >> 2, c16 = c & 3;
            CP_ASYNC16(sA + row * (APAD * 2) + c16 * 16,
                       Abase + (size_t)row * D_ORI + k0 + c16 * 8);
        }
        // W: 32 k-rows x 4 chunks = 128 -> threads 0..127
        if (tid < 128) {
            int krow = tid >> 2, c16 = tid & 3;
            CP_ASYNC16(sW + krow * (WPAD * 2) + c16 * 16,
                       Wbase + (size_t)(k0 + krow) * 32 + c16 * 8);
        }
        CP_COMMIT();
    };

    load_stage(0, 0);
    load_stage(1, 1);
    load_stage(2, 2);

    for (int k = 0; k < KITERS; k++) {
        const int slot = k & 3;

        if (k < KITERS - 2)      asm volatile("cp.async.wait_group 2;" ::: "memory");
        else if (k == KITERS - 2) asm volatile("cp.async.wait_group 1;" ::: "memory");
        else                      asm volatile("cp.async.wait_group 0;" ::: "memory");
        __syncthreads();

        if (k + 3 < KITERS) load_stage(k + 3, (k + 3) & 3);

        const uint32_t sA = sb + slot * BSTG2;
        const uint32_t sW = sA + ASTGB;

#pragma unroll
        for (int kk = 0; kk < 2; kk++) {
            uint32_t af[4];
            {
                const int arow = wid * 16 + (q & 1) * 8 + t;
                const int acol = kk * 16 + (q >> 1) * 8;
                ldsm_x4(af, sA + (arow * APAD + acol) * 2);
            }
            uint32_t bf[2][4];
#pragma unroll
            for (int p = 0; p < 2; p++) {
                const int krow = kk * 16 + (q & 1) * 8 + t;
                const int ncol = p * 16 + (q >> 1) * 8;
                ldsm_x4t(bf[p], sW + (krow * WPAD + ncol) * 2);
            }
#pragma unroll
            for (int nt = 0; nt < 4; nt++)
                mma_f16(acc[nt], af, &bf[nt >> 1][(nt & 1) * 2]);
        }
    }

    // ---- epilogue: stage logits to smem, then per-row softmax/dpo ----
    __syncthreads();
    float* sT = reinterpret_cast<float*>(smem);     // [128][33]
    {
        const int r0 = wid * 16 + (lane >> 2);
#pragma unroll
        for (int nt = 0; nt < 4; nt++) {
            const int c0 = nt * 8 + cq * 2;
            sT[r0 * 33 + c0]           = acc[nt][0];
            sT[r0 * 33 + c0 + 1]       = acc[nt][1];
            sT[(r0 + 8) * 33 + c0]     = acc[nt][2];
            sT[(r0 + 8) * 33 + c0 + 1] = acc[nt][3];
        }
    }
    __syncthreads();

    if (tid < 128) {
        const int row = tid;
        const size_t gn = (size_t)g * N_PR + n0 + row;
        const float* L = sT + row * 33;

#pragma unroll
        for (int f = 0; f < 4; f++)
            dpo_out[gn * 4 + f] = delta_rois[gn * 5 + 1 + f] + L[f];

        float m = L[4];
#pragma unroll
        for (int c = 1; c < NCLS; c++) m = fmaxf(m, L[4 + c]);
        float e[NCLS], s = 0.f;
#pragma unroll
        for (int c = 0; c < NCLS; c++) {
            e[c] = expf(L[4 + c] - m);
            s += e[c];
        }
        const float inv = 1.f / s;
#pragma unroll
        for (int c = 0; c < NCLS; c++)
            cls_out[gn * NCLS + c] = e[c] * inv;
    }
}

// ---------------------------------------------------------------------------
// Kernel C: softmax over G + final weighted sum
// ---------------------------------------------------------------------------
__global__ void finalize_kernel(const float* __restrict__ dpo,
                                float* __restrict__ out0,
                                float* __restrict__ out3)
{
    int n = blockIdx.x * blockDim.x + threadIdx.x;
    if (n >= N_PR) return;

#pragma unroll
    for (int f = 0; f < 4; f++) {
        float a[G_SL];
        float m = -1e30f;
#pragma unroll
        for (int g = 0; g < G_SL; g++) {
            a[g] = g_alpha[((size_t)g * N_PR + n) * 4 + f];
            m = fmaxf(m, a[g]);
        }
        float s = 0.f;
#pragma unroll
        for (int g = 0; g < G_SL; g++) {
            a[g] = expf(a[g] - m);
            s += a[g];
        }
        float inv = 1.f / s;
        float o = 0.f;
#pragma unroll
        for (int g = 0; g < G_SL; g++)
            o += dpo[((size_t)g * N_PR + n) * 4 + f] * a[g] * inv;
        out0[(size_t)n * 4 + f] = o;
    }

    {
        float a[G_SL];
        float m = -1e30f;
#pragma unroll
        for (int g = 0; g < G_SL; g++) {
            a[g] = g_alphacls[(size_t)g * N_PR + n];
            m = fmaxf(m, a[g]);
        }
        float s = 0.f;
#pragma unroll
        for (int g = 0; g < G_SL; g++) {
            a[g] = expf(a[g] - m);
            s += a[g];
        }
        float inv = 1.f / s;
#pragma unroll
        for (int g = 0; g < G_SL; g++)
            out3[(size_t)g * N_PR + n] = a[g] * inv;
    }
}

// ---------------------------------------------------------------------------
// Launch
// ---------------------------------------------------------------------------
extern "C" void kernel_launch(void* const* d_in, const int* in_sizes, int n_in,
                              void* d_out, int out_size)
{
    const float* features     = (const float*)d_in[0];
    const float* delta_rois   = (const float*)d_in[3];
    const float* attention    = (const float*)d_in[5];
    const float* alpha_w      = (const float*)d_in[6];
    const float* bbox_regress = (const float*)d_in[7];
    const float* alpha_w_cls  = (const float*)d_in[8];
    const float* cls_w        = (const float*)d_in[9];

    float* out  = (float*)d_out;
    float* out0 = out;
    float* out1 = out + OFF1;
    float* out2 = out + OFF2;
    float* out3 = out + OFF3;

    static bool attr_set = false;
    if (!attr_set) {
        cudaFuncSetAttribute(gemm_alpha_kernel,
                             cudaFuncAttributeMaxDynamicSharedMemorySize,
                             SMEM_GEMM_TOTAL);
        cudaFuncSetAttribute(branch_kernel,
                             cudaFuncAttributeMaxDynamicSharedMemorySize,
                             SMEM_BR_TOTAL);
        attr_set = true;
    }

    // zero the atomic accumulators (graph-capturable)
    void* pA; cudaGetSymbolAddress(&pA, g_alpha);
    void* pC; cudaGetSymbolAddress(&pC, g_alphacls);
    cudaMemsetAsync(pA, 0, sizeof(float) * (size_t)M_TOT * 4, 0);
    cudaMemsetAsync(pC, 0, sizeof(float) * (size_t)M_TOT, 0);

    // convert features and attention_feat to fp16; pack branch weights
    void* pAh; cudaGetSymbolAddress(&pAh, g_Ah);
    void* pBh; cudaGetSymbolAddress(&pBh, g_Bh);
    {
        int n8 = (M_TOT * D_ORI) / 8;
        convert_kernel<<<(n8 + 255) / 256, 256>>>(features, (__half*)pAh, n8);
        int b8 = (D_ORI * D_FEAT) / 8;
        convert_kernel<<<(b8 + 255) / 256, 256>>>(attention, (__half*)pBh, b8);
        pack_weights_kernel<<<(G_SL * D_ORI + 255) / 256, 256>>>(bbox_regress, cls_w);
    }

    // fused GEMM + relu + alpha projection
    gemm_alpha_kernel<<<dim3(D_FEAT / BN, M_TOT / BM), 512, SMEM_GEMM_TOTAL>>>(
        alpha_w, alpha_w_cls);

    // branch GEMM (offset + cls) + softmax + dpo
    branch_kernel<<<dim3(N_PR / 128, G_SL), 256, SMEM_BR_TOTAL>>>(
        delta_rois, out1, out2);

    // softmax over G + final output
    finalize_kernel<<<(N_PR + 255) / 256, 256>>>(out1, out0, out3);
}

// round 8
// speedup vs baseline: 1.7781x; 1.1254x over previous
#include <cuda_runtime.h>
#include <cuda_fp16.h>
#include <cstdint>

// ---------------------------------------------------------------------------
// Problem constants
// ---------------------------------------------------------------------------
#define G_SL   9
#define N_PR   4096
#define D_ORI  2048
#define D_FEAT 512
#define NCLS   21
#define M_TOT  (G_SL * N_PR)          // 36864

#define OFF1 (N_PR * 4)
#define OFF2 (OFF1 + G_SL * N_PR * 4)
#define OFF3 (OFF2 + G_SL * N_PR * NCLS)

// ---------------------------------------------------------------------------
// Device scratch (no cudaMalloc allowed)
// ---------------------------------------------------------------------------
__device__ __half g_Ah[(size_t)M_TOT * D_ORI];    // features fp16 (151 MB)
__device__ __half g_Bh[(size_t)D_ORI * D_FEAT];   // attention_feat fp16 [K][N]
__device__ __half g_Wh[(size_t)G_SL * D_ORI * 32];// packed branch weights fp16
__device__ float  g_alpha[(size_t)M_TOT * 4];     // alpha logits (atomic accum)
__device__ float  g_alphacls[(size_t)M_TOT];      // alpha_cls logits

// ---------------------------------------------------------------------------
// PTX helpers
// ---------------------------------------------------------------------------
__device__ __forceinline__ uint32_t smem_u32(const void* p) {
    uint32_t a;
    asm("{ .reg .u64 t; cvta.to.shared.u64 t, %1; cvt.u32.u64 %0, t; }"
        : "=r"(a) : "l"(p));
    return a;
}

#define CP_ASYNC16(dst, src) \
    asm volatile("cp.async.cg.shared.global [%0], [%1], 16;" :: "r"(dst), "l"(src) : "memory")
#define CP_COMMIT() asm volatile("cp.async.commit_group;" ::: "memory")

__device__ __forceinline__ void ldsm_x4(uint32_t* r, uint32_t addr) {
    asm volatile("ldmatrix.sync.aligned.m8n8.x4.shared.b16 {%0,%1,%2,%3}, [%4];"
        : "=r"(r[0]), "=r"(r[1]), "=r"(r[2]), "=r"(r[3]) : "r"(addr));
}
__device__ __forceinline__ void ldsm_x4t(uint32_t* r, uint32_t addr) {
    asm volatile("ldmatrix.sync.aligned.m8n8.x4.trans.shared.b16 {%0,%1,%2,%3}, [%4];"
        : "=r"(r[0]), "=r"(r[1]), "=r"(r[2]), "=r"(r[3]) : "r"(addr));
}

__device__ __forceinline__ void mma_f16(float* c, const uint32_t* a, const uint32_t* b) {
    asm volatile(
        "mma.sync.aligned.m16n8k16.row.col.f32.f16.f16.f32 "
        "{%0,%1,%2,%3}, {%4,%5,%6,%7}, {%8,%9}, {%0,%1,%2,%3};"
        : "+f"(c[0]), "+f"(c[1]), "+f"(c[2]), "+f"(c[3])
        : "r"(a[0]), "r"(a[1]), "r"(a[2]), "r"(a[3]),
          "r"(b[0]), "r"(b[1]));
}

// ---------------------------------------------------------------------------
// Conversion kernel: f32 -> f16, 8 elements per thread
// ---------------------------------------------------------------------------
__global__ void convert_kernel(const float* __restrict__ src,
                               __half* __restrict__ dst, int n8)
{
    int i = blockIdx.x * blockDim.x + threadIdx.x;
    if (i >= n8) return;
    float4 v0 = reinterpret_cast<const float4*>(src)[2 * i];
    float4 v1 = reinterpret_cast<const float4*>(src)[2 * i + 1];
    __half2 h0 = __floats2half2_rn(v0.x, v0.y);
    __half2 h1 = __floats2half2_rn(v0.z, v0.w);
    __half2 h2 = __floats2half2_rn(v1.x, v1.y);
    __half2 h3 = __floats2half2_rn(v1.z, v1.w);
    uint4 o;
    o.x = *reinterpret_cast<uint32_t*>(&h0);
    o.y = *reinterpret_cast<uint32_t*>(&h1);
    o.z = *reinterpret_cast<uint32_t*>(&h2);
    o.w = *reinterpret_cast<uint32_t*>(&h3);
    reinterpret_cast<uint4*>(dst)[i] = o;
}

// ---------------------------------------------------------------------------
// Prep: pack branch weights [G][2048 k][32 n] fp16 (cols 0-3 bbox, 4-24 cls)
// ---------------------------------------------------------------------------
__global__ void pack_weights_kernel(const float* __restrict__ bbox_w,
                                    const float* __restrict__ cls_w)
{
    int idx = blockIdx.x * blockDim.x + threadIdx.x;   // over G*2048
    if (idx >= G_SL * D_ORI) return;
    const int g = idx / D_ORI;
    const int d = idx % D_ORI;
    __half w[32];
#pragma unroll
    for (int c = 0; c < 4; c++)
        w[c] = __float2half_rn(bbox_w[((size_t)g * D_ORI + d) * 4 + c]);
#pragma unroll
    for (int c = 0; c < 21; c++)
        w[4 + c] = __float2half_rn(cls_w[((size_t)g * D_ORI + d) * 21 + c]);
#pragma unroll
    for (int c = 25; c < 32; c++) w[c] = __half(0.f);
    uint4* dst = reinterpret_cast<uint4*>(g_Wh + (size_t)idx * 32);
    const uint4* srcv = reinterpret_cast<const uint4*>(w);
#pragma unroll
    for (int i = 0; i < 4; i++) dst[i] = srcv[i];
}

// ---------------------------------------------------------------------------
// Kernel A: fused GEMM + relu + alpha projection (fp16 mma, ldmatrix).
//   CTA tile 128x128, BK=64, 3-stage cp.async, 256 threads (8 warps, 32x64),
//   2 CTAs/SM (independent barrier domains).
// ---------------------------------------------------------------------------
#define BM 128
#define BN 128
#define BK 64
#define APAD 72
#define BPAD 136
#define KITERS (D_ORI / BK)                  // 32
#define ASTGB (BM * APAD * 2)                // 18432 bytes
#define BSTGB (BK * BPAD * 2)                // 17408 bytes
#define STGB  (ASTGB + BSTGB)                // 35840 bytes
#define SMEM_GEMM_TOTAL (3 * STGB)           // 107520 bytes

__global__ __launch_bounds__(256, 2)
void gemm_alpha_kernel(const float* __restrict__ alpha_w,      // [G, 512, 4]
                       const float* __restrict__ alpha_w_cls)  // [G, 512, 1]
{
    extern __shared__ char smem[];
    const uint32_t sb = smem_u32(smem);
    const int tid  = threadIdx.x;
    const int wid  = tid >> 5;     // 0..7
    const int lane = tid & 31;
    const int r  = lane >> 2;
    const int cq = lane & 3;
    const int q  = lane >> 3;
    const int t  = lane & 7;

    const int m0 = blockIdx.y * BM;
    const int n0 = blockIdx.x * BN;
    const int g  = blockIdx.y >> 5;
    const int mbase = (wid & 3) * 32;     // 4 warp rows of 32
    const int nbase = (wid >> 2) * 64;    // 2 warp cols of 64

    const __half* Abase = g_Ah + (size_t)m0 * D_ORI;

    float acc[2][8][4];
#pragma unroll
    for (int mt = 0; mt < 2; mt++)
#pragma unroll
        for (int nt = 0; nt < 8; nt++)
#pragma unroll
            for (int i = 0; i < 4; i++) acc[mt][nt][i] = 0.f;

    auto load_stage = [&](int kiter, int slot) {
        const int k0 = kiter * BK;
        const uint32_t sA = sb + slot * STGB;
        const uint32_t sB = sA + ASTGB;
        // A: 128 rows x 8 chunks (128B) = 1024 -> 4 per thread
#pragma unroll
        for (int i = 0; i < 4; i++) {
            int c = tid + i * 256;
            int row = c >> 3, c16 = c & 7;
            CP_ASYNC16(sA + row * (APAD * 2) + c16 * 16,
                       Abase + (size_t)row * D_ORI + k0 + c16 * 8);
        }
        // B: 64 k-rows x 16 chunks (256B) = 1024 -> 4 per thread
#pragma unroll
        for (int i = 0; i < 4; i++) {
            int c = tid + i * 256;
            int krow = c >> 4, c16 = c & 15;
            CP_ASYNC16(sB + krow * (BPAD * 2) + c16 * 16,
                       g_Bh + (size_t)(k0 + krow) * D_FEAT + n0 + c16 * 8);
        }
        CP_COMMIT();
    };

    load_stage(0, 0);
    load_stage(1, 1);

    for (int k = 0; k < KITERS; k++) {
        const int slot = k % 3;

        if (k < KITERS - 2) asm volatile("cp.async.wait_group 1;" ::: "memory");
        else                asm volatile("cp.async.wait_group 0;" ::: "memory");
        __syncthreads();

        if (k + 2 < KITERS) load_stage(k + 2, (k + 2) % 3);

        const uint32_t sA = sb + slot * STGB;
        const uint32_t sB = sA + ASTGB;

#pragma unroll
        for (int kk = 0; kk < 4; kk++) {
            uint32_t af[2][4];
#pragma unroll
            for (int mt = 0; mt < 2; mt++) {
                const int arow = mbase + mt * 16 + (q & 1) * 8 + t;
                const int acol = kk * 16 + (q >> 1) * 8;
                ldsm_x4(af[mt], sA + (arow * APAD + acol) * 2);
            }
            uint32_t bf[4][4];
#pragma unroll
            for (int p = 0; p < 4; p++) {
                const int krow = kk * 16 + (q & 1) * 8 + t;
                const int ncol = nbase + p * 16 + (q >> 1) * 8;
                ldsm_x4t(bf[p], sB + (krow * BPAD + ncol) * 2);
            }
#pragma unroll
            for (int mt = 0; mt < 2; mt++)
#pragma unroll
                for (int nt = 0; nt < 8; nt++)
                    mma_f16(acc[mt][nt], af[mt], &bf[nt >> 1][(nt & 1) * 2]);
        }
    }

    // ---- relu in registers ----
#pragma unroll
    for (int mt = 0; mt < 2; mt++)
#pragma unroll
        for (int nt = 0; nt < 8; nt++)
#pragma unroll
            for (int i = 0; i < 4; i++) acc[mt][nt][i] = fmaxf(acc[mt][nt][i], 0.f);

    // ---- stage alpha weights for this CTA's 128 columns ----
    __syncthreads();
    float* wA = reinterpret_cast<float*>(smem);     // [128][6]
    if (tid < 128) {
        const int c = tid;
#pragma unroll
        for (int f = 0; f < 4; f++)
            wA[c * 6 + f] = alpha_w[((size_t)g * D_FEAT + n0 + c) * 4 + f];
        wA[c * 6 + 4] = alpha_w_cls[(size_t)g * D_FEAT + n0 + c];
    }
    __syncthreads();

    // ---- alpha partials: per row dot over 16 owned cols, quad-reduce ----
#pragma unroll
    for (int mt = 0; mt < 2; mt++) {
#pragma unroll
        for (int h = 0; h < 2; h++) {
            float s[5] = {0.f, 0.f, 0.f, 0.f, 0.f};
#pragma unroll
            for (int nt = 0; nt < 8; nt++) {
                const int col = nbase + nt * 8 + cq * 2;
                const float v0 = acc[mt][nt][2 * h + 0];
                const float v1 = acc[mt][nt][2 * h + 1];
#pragma unroll
                for (int f = 0; f < 5; f++)
                    s[f] += v0 * wA[col * 6 + f] + v1 * wA[(col + 1) * 6 + f];
            }
#pragma unroll
            for (int f = 0; f < 5; f++) {
                s[f] += __shfl_xor_sync(0xFFFFFFFF, s[f], 1);
                s[f] += __shfl_xor_sync(0xFFFFFFFF, s[f], 2);
            }
            if (cq == 0) {
                const int grow = m0 + mbase + mt * 16 + h * 8 + r;
#pragma unroll
                for (int f = 0; f < 4; f++)
                    atomicAdd(&g_alpha[(size_t)grow * 4 + f], s[f]);
                atomicAdd(&g_alphacls[grow], s[4]);
            }
        }
    }
}

// ---------------------------------------------------------------------------
// Kernel B: branch GEMM (fp16 mma): [128 x 2048] @ [2048 x 32] per (g, tile).
//   A and W both via 4-stage cp.async (packed fp16 weights). One sync/iter.
// ---------------------------------------------------------------------------
#define BRK 32
#define BRKITERS (D_ORI / BRK)                    // 64
#define BAPAD 40
#define BASTGB (128 * BAPAD * 2)                  // 10240 bytes
#define WPAD 40
#define WSTGB (BRK * WPAD * 2)                    // 2560 bytes
#define BSTG2 (BASTGB + WSTGB)                    // 12800 bytes
#define SMEM_BR_TOTAL (4 * BSTG2)                 // 51200 bytes

__global__ __launch_bounds__(256, 2)
void branch_kernel(const float* __restrict__ delta_rois,  // [G, N, 5]
                   float* __restrict__ dpo_out,            // out1 [G,N,4]
                   float* __restrict__ cls_out)            // out2 [G,N,21]
{
    extern __shared__ char smem[];
    const uint32_t sb = smem_u32(smem);
    const int tid  = threadIdx.x;
    const int wid  = tid >> 5;
    const int lane = tid & 31;
    const int cq = lane & 3;
    const int q  = lane >> 3;
    const int t  = lane & 7;

    const int g  = blockIdx.y;
    const int n0 = blockIdx.x * 128;

    const __half* Abase = g_Ah + ((size_t)g * N_PR + n0) * D_ORI;
    const __half* Wbase = g_Wh + (size_t)g * D_ORI * 32;

    float acc[4][4];
#pragma unroll
    for (int nt = 0; nt < 4; nt++)
#pragma unroll
        for (int i = 0; i < 4; i++) acc[nt][i] = 0.f;

    auto load_stage = [&](int kiter, int slot) {
        const int k0 = kiter * BRK;
        const uint32_t sA = sb + slot * BSTG2;
        const uint32_t sW = sA + BASTGB;
#pragma unroll
        for (int i = 0; i < 2; i++) {
            int c = tid + i * 256;
            int row = c >> 2, c16 = c & 3;
            CP_ASYNC16(sA + row * (BAPAD * 2) + c16 * 16,
                       Abase + (size_t)row * D_ORI + k0 + c16 * 8);
        }
        if (tid < 128) {
            int krow = tid >> 2, c16 = tid & 3;
            CP_ASYNC16(sW + krow * (WPAD * 2) + c16 * 16,
                       Wbase + (size_t)(k0 + krow) * 32 + c16 * 8);
        }
        CP_COMMIT();
    };

    load_stage(0, 0);
    load_stage(1, 1);
    load_stage(2, 2);

    for (int k = 0; k < BRKITERS; k++) {
        const int slot = k & 3;

        if (k < BRKITERS - 2)      asm volatile("cp.async.wait_group 2;" ::: "memory");
        else if (k == BRKITERS - 2) asm volatile("cp.async.wait_group 1;" ::: "memory");
        else                        asm volatile("cp.async.wait_group 0;" ::: "memory");
        __syncthreads();

        if (k + 3 < BRKITERS) load_stage(k + 3, (k + 3) & 3);

        const uint32_t sA = sb + slot * BSTG2;
        const uint32_t sW = sA + BASTGB;

#pragma unroll
        for (int kk = 0; kk < 2; kk++) {
            uint32_t af[4];
            {
                const int arow = wid * 16 + (q & 1) * 8 + t;
                const int acol = kk * 16 + (q >> 1) * 8;
                ldsm_x4(af, sA + (arow * BAPAD + acol) * 2);
            }
            uint32_t bf[2][4];
#pragma unroll
            for (int p = 0; p < 2; p++) {
                const int krow = kk * 16 + (q & 1) * 8 + t;
                const int ncol = p * 16 + (q >> 1) * 8;
                ldsm_x4t(bf[p], sW + (krow * WPAD + ncol) * 2);
            }
#pragma unroll
            for (int nt = 0; nt < 4; nt++)
                mma_f16(acc[nt], af, &bf[nt >> 1][(nt & 1) * 2]);
        }
    }

    // ---- epilogue: stage logits to smem, then per-row softmax/dpo ----
    __syncthreads();
    float* sT = reinterpret_cast<float*>(smem);     // [128][33]
    {
        const int r0 = wid * 16 + (lane >> 2);
#pragma unroll
        for (int nt = 0; nt < 4; nt++) {
            const int c0 = nt * 8 + cq * 2;
            sT[r0 * 33 + c0]           = acc[nt][0];
            sT[r0 * 33 + c0 + 1]       = acc[nt][1];
            sT[(r0 + 8) * 33 + c0]     = acc[nt][2];
            sT[(r0 + 8) * 33 + c0 + 1] = acc[nt][3];
        }
    }
    __syncthreads();

    if (tid < 128) {
        const int row = tid;
        const size_t gn = (size_t)g * N_PR + n0 + row;
        const float* L = sT + row * 33;

#pragma unroll
        for (int f = 0; f < 4; f++)
            dpo_out[gn * 4 + f] = delta_rois[gn * 5 + 1 + f] + L[f];

        float m = L[4];
#pragma unroll
        for (int c = 1; c < NCLS; c++) m = fmaxf(m, L[4 + c]);
        float e[NCLS], s = 0.f;
#pragma unroll
        for (int c = 0; c < NCLS; c++) {
            e[c] = expf(L[4 + c] - m);
            s += e[c];
        }
        const float inv = 1.f / s;
#pragma unroll
        for (int c = 0; c < NCLS; c++)
            cls_out[gn * NCLS + c] = e[c] * inv;
    }
}

// ---------------------------------------------------------------------------
// Kernel C: softmax over G + final weighted sum
// ---------------------------------------------------------------------------
__global__ void finalize_kernel(const float* __restrict__ dpo,
                                float* __restrict__ out0,
                                float* __restrict__ out3)
{
    int n = blockIdx.x * blockDim.x + threadIdx.x;
    if (n >= N_PR) return;

#pragma unroll
    for (int f = 0; f < 4; f++) {
        float a[G_SL];
        float m = -1e30f;
#pragma unroll
        for (int g = 0; g < G_SL; g++) {
            a[g] = g_alpha[((size_t)g * N_PR + n) * 4 + f];
            m = fmaxf(m, a[g]);
        }
        float s = 0.f;
#pragma unroll
        for (int g = 0; g < G_SL; g++) {
            a[g] = expf(a[g] - m);
            s += a[g];
        }
        float inv = 1.f / s;
        float o = 0.f;
#pragma unroll
        for (int g = 0; g < G_SL; g++)
            o += dpo[((size_t)g * N_PR + n) * 4 + f] * a[g] * inv;
        out0[(size_t)n * 4 + f] = o;
    }

    {
        float a[G_SL];
        float m = -1e30f;
#pragma unroll
        for (int g = 0; g < G_SL; g++) {
            a[g] = g_alphacls[(size_t)g * N_PR + n];
            m = fmaxf(m, a[g]);
        }
        float s = 0.f;
#pragma unroll
        for (int g = 0; g < G_SL; g++) {
            a[g] = expf(a[g] - m);
            s += a[g];
        }
        float inv = 1.f / s;
#pragma unroll
        for (int g = 0; g < G_SL; g++)
            out3[(size_t)g * N_PR + n] = a[g] * inv;
    }
}

// ---------------------------------------------------------------------------
// Launch
// ---------------------------------------------------------------------------
extern "C" void kernel_launch(void* const* d_in, const int* in_sizes, int n_in,
                              void* d_out, int out_size)
{
    const float* features     = (const float*)d_in[0];
    const float* delta_rois   = (const float*)d_in[3];
    const float* attention    = (const float*)d_in[5];
    const float* alpha_w      = (const float*)d_in[6];
    const float* bbox_regress = (const float*)d_in[7];
    const float* alpha_w_cls  = (const float*)d_in[8];
    const float* cls_w        = (const float*)d_in[9];

    float* out  = (float*)d_out;
    float* out0 = out;
    float* out1 = out + OFF1;
    float* out2 = out + OFF2;
    float* out3 = out + OFF3;

    static bool attr_set = false;
    if (!attr_set) {
        cudaFuncSetAttribute(gemm_alpha_kernel,
                             cudaFuncAttributeMaxDynamicSharedMemorySize,
                             SMEM_GEMM_TOTAL);
        cudaFuncSetAttribute(branch_kernel,
                             cudaFuncAttributeMaxDynamicSharedMemorySize,
                             SMEM_BR_TOTAL);
        attr_set = true;
    }

    // zero the atomic accumulators (graph-capturable)
    void* pA; cudaGetSymbolAddress(&pA, g_alpha);
    void* pC; cudaGetSymbolAddress(&pC, g_alphacls);
    cudaMemsetAsync(pA, 0, sizeof(float) * (size_t)M_TOT * 4, 0);
    cudaMemsetAsync(pC, 0, sizeof(float) * (size_t)M_TOT, 0);

    // convert features and attention_feat to fp16; pack branch weights
    void* pAh; cudaGetSymbolAddress(&pAh, g_Ah);
    void* pBh; cudaGetSymbolAddress(&pBh, g_Bh);
    {
        int n8 = (M_TOT * D_ORI) / 8;
        convert_kernel<<<(n8 + 255) / 256, 256>>>(features, (__half*)pAh, n8);
        int b8 = (D_ORI * D_FEAT) / 8;
        convert_kernel<<<(b8 + 255) / 256, 256>>>(attention, (__half*)pBh, b8);
        pack_weights_kernel<<<(G_SL * D_ORI + 255) / 256, 256>>>(bbox_regress, cls_w);
    }

    // fused GEMM + relu + alpha projection (128x128 tiles, 2 CTAs/SM)
    gemm_alpha_kernel<<<dim3(D_FEAT / BN, M_TOT / BM), 256, SMEM_GEMM_TOTAL>>>(
        alpha_w, alpha_w_cls);

    // branch GEMM (offset + cls) + softmax + dpo
    branch_kernel<<<dim3(N_PR / 128, G_SL), 256, SMEM_BR_TOTAL>>>(
        delta_rois, out1, out2);

    // softmax over G + final output
    finalize_kernel<<<(N_PR + 255) / 256, 256>>>(out1, out0, out3);
}